// round 17
// baseline (speedup 1.0000x reference)
#include <cuda_runtime.h>
#include <math_constants.h>

// Problem constants
#define NUM_VARS 64
#define KK       32
#define NUM_CATS 256
#define NUM_INPUT (NUM_VARS * KK)   // 2048
#define LL       4
#define EE       16384
#define NN       8192
#define CC       4
#define BB       1024
#define Q16      128                // uint4-groups per row (1024 u16 = 128 x 16B)
#define TOTAL_NODES (NUM_INPUT + LL * NN)  // 34816
#define NCHUNK   128                // root reduction chunks (chain length 64)
#define MAX_NPB  14                 // max nodes per block per layer

#define GRID_BLOCKS 592             // 4 blocks/SM on 148 SMs — co-resident
#define THREADS     256
#define NTHREADS    (GRID_BLOCKS * THREADS)

#define LOG2E 1.4426950408889634f
#define LN2   0.6931471805599453f
#define QSCALE   128.0f             // u16 = -v_log2 * 128, clamp 32767
#define INVQ     (1.0f / 128.0f)
#define MAGIC    8388608.0f         // 2^23
#define MAGIC_HI 0x4B000000u

// Node pool quantized to u16 (71.3 MB — fully L2-resident)
__device__ unsigned short g_node_q[(size_t)TOTAL_NODES * BB];
__device__ float g_partial[NCHUNK * BB];
__device__ uint2 g_pairs[LL * NN * CC];   // row offsets pre-scaled by Q16
__device__ float4 g_wqf[LL * NN];         // pre-scaled weights: w*LOG2E + MAGIC*INVQ

// Grid barrier
__device__ unsigned g_bar_count;
__device__ volatile unsigned g_bar_gen;

__device__ __forceinline__ void grid_sync() {
    __syncthreads();
    if (threadIdx.x == 0) {
        __threadfence();                      // release
        unsigned gen = g_bar_gen;
        if (atomicAdd(&g_bar_count, 1u) == GRID_BLOCKS - 1u) {
            g_bar_count = 0;
            __threadfence();
            g_bar_gen = gen + 1u;
        } else {
            while (g_bar_gen == gen) { }
        }
        __threadfence();                      // acquire: SM-wide L1D invalidate
    }
    __syncthreads();
}

__device__ __forceinline__ float ex2(float x) {
    float r; asm("ex2.approx.ftz.f32 %0, %1;" : "=f"(r) : "f"(x)); return r;
}
__device__ __forceinline__ float lg2(float x) {
    float r; asm("lg2.approx.ftz.f32 %0, %1;" : "=f"(r) : "f"(x)); return r;
}
__device__ __forceinline__ float dec_lo(unsigned s, float wq) {
    const float f = __uint_as_float(__byte_perm(s, MAGIC_HI, 0x7610));
    return fmaf(f, -INVQ, wq);
}
__device__ __forceinline__ float dec_hi(unsigned s, float wq) {
    const float f = __uint_as_float(__byte_perm(s, MAGIC_HI, 0x7632));
    return fmaf(f, -INVQ, wq);
}
__device__ __forceinline__ unsigned enc1(float v_log2) {
    unsigned q = __float2uint_rn(-v_log2 * QSCALE);
    return umin(q, 32767u);
}

// LSE over 4 children for one u16x2 word (2 batch columns) -> packed u16x2 out.
// Integer-reference variant: m = min of quantized pair-sums (weights excluded),
// t_c = w2_c - d_c/128 <= 0, s = sum 2^t in (0,4], out = m + round(-128*lg2(s)).
__device__ __forceinline__ unsigned lse_pack(unsigned s0, unsigned s1,
                                             unsigned s2, unsigned s3,
                                             float wq0, float wq1,
                                             float wq2, float wq3) {
    const unsigned m  = __vminu2(__vminu2(s0, s1), __vminu2(s2, s3));
    const unsigned d0 = __vsub2(s0, m);
    const unsigned d1 = __vsub2(s1, m);
    const unsigned d2 = __vsub2(s2, m);
    const unsigned d3 = __vsub2(s3, m);

    const float sl = ex2(dec_lo(d0, wq0)) + ex2(dec_lo(d1, wq1))
                   + ex2(dec_lo(d2, wq2)) + ex2(dec_lo(d3, wq3));
    const float sh = ex2(dec_hi(d0, wq0)) + ex2(dec_hi(d1, wq1))
                   + ex2(dec_hi(d2, wq2)) + ex2(dec_hi(d3, wq3));

    // v = round(-128*lg2(s)) in low 16 bits via 2^23 magic (v >= -256, small)
    const unsigned ul = __float_as_uint(fmaf(lg2(sl), -QSCALE, MAGIC));
    const unsigned uh = __float_as_uint(fmaf(lg2(sh), -QSCALE, MAGIC));
    const unsigned v  = __byte_perm(ul, uh, 0x5410);
    // saturating s16 add (caps at 32767), then clamp below at 0
    return __vmaxs2(__vaddss2(m, v), 0u);
}

__global__ void __launch_bounds__(THREADS, 4)
circuit_kernel(const int* __restrict__ inputs,
               const float* __restrict__ input_logp,
               const int2* __restrict__ prod_ids,     // (L, E)
               const int* __restrict__ sum_ch_ids,    // (L, N, C)
               const float4* __restrict__ sum_logw,   // (L, N) as float4
               const float* __restrict__ root_logw,   // (N,)
               float* __restrict__ out) {
    const int gtid = blockIdx.x * THREADS + threadIdx.x;

    __shared__ unsigned s_pairs[MAX_NPB * 8];
    __shared__ float4   s_w[MAX_NPB];

    // ---------- Phase 0: input quantize + resolve + weight prescale ------------
    for (int idx = gtid; idx < NUM_INPUT * BB; idx += NTHREADS) {
        const int v = idx >> 15;
        const int k = (idx >> 10) & (KK - 1);
        const int b = idx & (BB - 1);
        const int cat = __ldg(inputs + b * NUM_VARS + v);
        const float lp2 = __ldg(input_logp + ((v * KK + k) << 8) + cat) * LOG2E;
        g_node_q[idx] = (unsigned short)enc1(lp2);
    }
    for (int idx = gtid; idx < LL * NN * CC; idx += NTHREADS) {
        const int l = idx / (NN * CC);
        const int e = __ldg(sum_ch_ids + idx);
        const int2 p = __ldg(prod_ids + (size_t)l * EE + e);
        g_pairs[idx] = make_uint2((unsigned)p.x * Q16, (unsigned)p.y * Q16);
    }
    for (int idx = gtid; idx < LL * NN; idx += NTHREADS) {
        const float4 w = __ldg(sum_logw + idx);
        float4 wq;
        wq.x = fmaf(w.x, LOG2E, MAGIC * INVQ);
        wq.y = fmaf(w.y, LOG2E, MAGIC * INVQ);
        wq.z = fmaf(w.z, LOG2E, MAGIC * INVQ);
        wq.w = fmaf(w.w, LOG2E, MAGIC * INVQ);
        g_wqf[idx] = wq;
    }
    grid_sync();

    // ---------- Phases 1..4: sum layers — uint4 gathers, half-block per node ---
    const uint4* nq = reinterpret_cast<const uint4*>(g_node_q);
    uint4* nqo = reinterpret_cast<uint4*>(g_node_q);
    const unsigned c16 = threadIdx.x & 127;   // uint4-column 0..127
    const int half = threadIdx.x >> 7;        // 0 or 1: which node of the pair

    const int start = (int)(((long long)blockIdx.x * NN) / GRID_BLOCKS);
    const int end   = (int)(((long long)(blockIdx.x + 1) * NN) / GRID_BLOCKS);
    const int cnt   = end - start;            // 13 or 14
    const int iters = (cnt + 1) >> 1;

    for (int l = 0; l < LL; l++) {
        const int out_base = NUM_INPUT + l * NN;
        const unsigned* gp = reinterpret_cast<const unsigned*>(g_pairs + (size_t)l * NN * CC);
        const float* gw = reinterpret_cast<const float*>(g_wqf + (size_t)l * NN);

        for (int t = threadIdx.x; t < cnt * 8; t += THREADS)
            s_pairs[t] = gp[start * 8 + t];
        for (int t = threadIdx.x; t < cnt * 4; t += THREADS)
            reinterpret_cast<float*>(s_w)[t] = gw[start * 4 + t];
        __syncthreads();

#pragma unroll 2
        for (int i = 0; i < iters; i++) {
            const int local = i * 2 + half;
            const int n = start + local;
            if (n < end) {
                const uint4 pa = *reinterpret_cast<const uint4*>(s_pairs + local * 8);
                const uint4 pb = *reinterpret_cast<const uint4*>(s_pairs + local * 8 + 4);
                const float4 wq = s_w[local];

                const uint4 a0 = __ldg(nq + pa.x + c16);
                const uint4 q0 = __ldg(nq + pa.y + c16);
                const uint4 a1 = __ldg(nq + pa.z + c16);
                const uint4 q1 = __ldg(nq + pa.w + c16);
                const uint4 a2 = __ldg(nq + pb.x + c16);
                const uint4 q2 = __ldg(nq + pb.y + c16);
                const uint4 a3 = __ldg(nq + pb.z + c16);
                const uint4 q3 = __ldg(nq + pb.w + c16);

                uint4 o;
                o.x = lse_pack(__vadd2(a0.x, q0.x), __vadd2(a1.x, q1.x),
                               __vadd2(a2.x, q2.x), __vadd2(a3.x, q3.x),
                               wq.x, wq.y, wq.z, wq.w);
                o.y = lse_pack(__vadd2(a0.y, q0.y), __vadd2(a1.y, q1.y),
                               __vadd2(a2.y, q2.y), __vadd2(a3.y, q3.y),
                               wq.x, wq.y, wq.z, wq.w);
                o.z = lse_pack(__vadd2(a0.z, q0.z), __vadd2(a1.z, q1.z),
                               __vadd2(a2.z, q2.z), __vadd2(a3.z, q3.z),
                               wq.x, wq.y, wq.z, wq.w);
                o.w = lse_pack(__vadd2(a0.w, q0.w), __vadd2(a1.w, q1.w),
                               __vadd2(a2.w, q2.w), __vadd2(a3.w, q3.w),
                               wq.x, wq.y, wq.z, wq.w);

                nqo[(unsigned)(out_base + n) * Q16 + c16] = o;
            }
        }
        grid_sync();
    }

    // ---------- Phase 5: root partial logsumexp (decode u16, float) -----------
    {
        const unsigned short* last = g_node_q + (size_t)(NUM_INPUT + (LL - 1) * NN) * BB;
        const int idx = gtid;
        if (idx < NCHUNK * BB) {
            const int chunk = idx >> 10;
            const int b = idx & (BB - 1);
            const int n0 = chunk * (NN / NCHUNK);
            float m = -CUDART_INF_F, s = 0.f;
#pragma unroll 4
            for (int i2 = 0; i2 < NN / NCHUNK; i2++) {
                const int n = n0 + i2;
                const float nv = -(float)last[(unsigned)n * BB + b] * INVQ;
                const float x = fmaf(__ldg(root_logw + n), LOG2E, nv);
                const float mn = fmaxf(m, x);
                s = s * ex2(m - mn) + ex2(x - mn);
                m = mn;
            }
            g_partial[chunk * BB + b] = m + lg2(s);
        }
    }
    grid_sync();

    // ---------- Phase 6: final combine (warp per column, 128 partials) --------
    {
        const int wgid = gtid >> 5;
        const int lane = gtid & 31;
        if (wgid < BB) {
            const int b = wgid;
            const float x0 = g_partial[lane * BB + b];
            const float x1 = g_partial[(lane + 32) * BB + b];
            const float x2 = g_partial[(lane + 64) * BB + b];
            const float x3 = g_partial[(lane + 96) * BB + b];
            float m = fmaxf(fmaxf(x0, x1), fmaxf(x2, x3));
#pragma unroll
            for (int o = 16; o > 0; o >>= 1)
                m = fmaxf(m, __shfl_xor_sync(0xFFFFFFFF, m, o));
            float s = ex2(x0 - m) + ex2(x1 - m) + ex2(x2 - m) + ex2(x3 - m);
#pragma unroll
            for (int o = 16; o > 0; o >>= 1)
                s += __shfl_xor_sync(0xFFFFFFFF, s, o);
            if (lane == 0) out[b] = (m + lg2(s)) * LN2;
        }
    }
}

// ---------------------------------------------------------------------------
extern "C" void kernel_launch(void* const* d_in, const int* in_sizes, int n_in,
                              void* d_out, int out_size) {
    const int*   inputs     = (const int*)  d_in[0];
    const float* input_logp = (const float*)d_in[1];
    const int*   prod_ids   = (const int*)  d_in[2];  // (L, E, 2)
    const int*   sum_ch_ids = (const int*)  d_in[3];  // (L, N, C)
    const float* sum_logw   = (const float*)d_in[4];  // (L, N, C)
    const float* root_logw  = (const float*)d_in[5];  // (N,)
    float* out = (float*)d_out;

    circuit_kernel<<<GRID_BLOCKS, THREADS>>>(
        inputs, input_logp,
        reinterpret_cast<const int2*>(prod_ids),
        sum_ch_ids,
        reinterpret_cast<const float4*>(sum_logw),
        root_logw, out);
}